// round 15
// baseline (speedup 1.0000x reference)
#include <cuda_runtime.h>
#include <cuda_bf16.h>
#include <mma.h>
#include <cstdint>

using namespace nvcuda;

#define N_NODES 40000
#define N_EDGES 640000
#define DIN 128
#define DH 128
#define DOUT 64
#define PAD 64                                       // max in-degree slots per node

#define NT ((N_NODES + 127) / 128)                   // 313 M-tiles
#define GEMM_GRID 152

// ---------------- scratch (no allocations allowed) ----------------
__device__ int   g_is64;
__device__ int   g_cnt[N_NODES];
__device__ __align__(16) int g_eslots[(size_t)N_NODES * PAD];   // padded adjacency (src ids)
__device__ float g_dinv[N_NODES];
__device__ float g_h1[(size_t)N_NODES * DH];         // gemm1 out (fp32)
__device__ float g_h2[(size_t)N_NODES * DOUT];       // gemm2 out (fp32)
// bf16 hi/lo split operands
__device__ __align__(16) __nv_bfloat16 g_xhi[(size_t)N_NODES * DIN];
__device__ __align__(16) __nv_bfloat16 g_xlo[(size_t)N_NODES * DIN];
__device__ __align__(16) __nv_bfloat16 g_a2hi[(size_t)N_NODES * DH];
__device__ __align__(16) __nv_bfloat16 g_a2lo[(size_t)N_NODES * DH];
__device__ __align__(16) __nv_bfloat16 g_b1hi[DIN * DH];   // row-major [k][n]
__device__ __align__(16) __nv_bfloat16 g_b1lo[DIN * DH];
__device__ __align__(16) __nv_bfloat16 g_b2hi[DH * DOUT];
__device__ __align__(16) __nv_bfloat16 g_b2lo[DH * DOUT];

// ---------------- helpers ----------------
__device__ __forceinline__ uint32_t smem_u32(const void* p) {
    uint32_t a;
    asm("{ .reg .u64 t; cvta.to.shared.u64 t, %1; cvt.u32.u64 %0, t; }" : "=r"(a) : "l"(p));
    return a;
}
__device__ __forceinline__ void cp16(uint32_t dst, const void* src, int sz) {
    asm volatile("cp.async.cg.shared.global [%0], [%1], 16, %2;"
                 :: "r"(dst), "l"(src), "r"(sz) : "memory");
}
#define CP_COMMIT() asm volatile("cp.async.commit_group;" ::: "memory")
#define CP_WAIT1()  asm volatile("cp.async.wait_group 1;" ::: "memory")

__device__ __forceinline__ void split2(float a, float b, uint32_t& hi, uint32_t& lo) {
    __nv_bfloat16 ha = __float2bfloat16(a), hb = __float2bfloat16(b);
    float ra = a - __bfloat162float(ha), rb = b - __bfloat162float(hb);
    __nv_bfloat16 la = __float2bfloat16(ra), lb = __float2bfloat16(rb);
    hi = (uint32_t)__bfloat16_as_ushort(ha) | ((uint32_t)__bfloat16_as_ushort(hb) << 16);
    lo = (uint32_t)__bfloat16_as_ushort(la) | ((uint32_t)__bfloat16_as_ushort(lb) << 16);
}

// ---------------- init: zero counts + dtype detect + weight split (fused) ----------------
__global__ void k_init(const int* __restrict__ ei,
                       const float* __restrict__ W1, const float* __restrict__ W2) {
    int i = blockIdx.x * blockDim.x + threadIdx.x;
    if (i < N_NODES) g_cnt[i] = 0;
    if (i < DIN * DH) {
        float v = W1[i];
        __nv_bfloat16 h = __float2bfloat16(v);
        g_b1hi[i] = h;
        g_b1lo[i] = __float2bfloat16(v - __bfloat162float(h));
    }
    int j = i - DIN * DH;
    if (j >= 0 && j < DH * DOUT) {
        float v = W2[j];
        __nv_bfloat16 h = __float2bfloat16(v);
        g_b2hi[j] = h;
        g_b2lo[j] = __float2bfloat16(v - __bfloat162float(h));
    }
    if (blockIdx.x == 0) {
        __shared__ int any_nz;
        if (threadIdx.x == 0) any_nz = 0;
        __syncthreads();
        int nz = 0;
        for (int t = threadIdx.x; t < 4096; t += blockDim.x)
            if (ei[2 * t + 1] != 0) nz = 1;
        if (nz) any_nz = 1;
        __syncthreads();
        if (threadIdx.x == 0) g_is64 = any_nz ? 0 : 1;
    }
}

__device__ __forceinline__ int edge_idx(const void* ei, int which, int e, int is64) {
    if (is64) return (int)((const long long*)ei)[(size_t)which * N_EDGES + e];
    return ((const int*)ei)[which * N_EDGES + e];
}

// ---------------- x -> hi/lo bf16 ----------------
__global__ void k_cvtx(const float* __restrict__ x) {
    int idx = blockIdx.x * blockDim.x + threadIdx.x;          // float4 index
    if (idx < N_NODES * DIN / 4) {
        float4 v = ((const float4*)x)[idx];
        uint2 h, l;
        split2(v.x, v.y, h.x, l.x);
        split2(v.z, v.w, h.y, l.y);
        ((uint2*)g_xhi)[idx] = h;
        ((uint2*)g_xlo)[idx] = l;
    }
}

// ---------------- padded-list fill + dinv ----------------
__global__ void k_fill(const void* __restrict__ ei) {
    int e = blockIdx.x * blockDim.x + threadIdx.x;
    if (e < N_EDGES) {
        int is64 = g_is64;
        int d = edge_idx(ei, 1, e, is64);
        int s = edge_idx(ei, 0, e, is64);
        if ((unsigned)d < N_NODES && (unsigned)s < N_NODES) {
            int pos = atomicAdd(&g_cnt[d], 1);
            if (pos < PAD) g_eslots[(size_t)d * PAD + pos] = s;
        }
    }
}

__global__ void k_dinv() {
    int i = blockIdx.x * blockDim.x + threadIdx.x;
    if (i < N_NODES) g_dinv[i] = rsqrtf((float)(g_cnt[i] + 1));   // +1 self-loop
}

// ---------------- pipelined WMMA bf16 GEMM: C[40000,N] = A[40000,128] @ B[128,N] ----------------
// A pre-split bf16 hi/lo in GMEM; cp.async double-buffered A SMEM; B SMEM-resident.
// fp32 accum: acc += Ah*Bh + Ah*Bl + Al*Bh. 512 threads, persistent blocks.
template <int N>
__global__ void __launch_bounds__(512, 1) k_gemm_pipe(
    const __nv_bfloat16* __restrict__ Ahi, const __nv_bfloat16* __restrict__ Alo,
    const __nv_bfloat16* __restrict__ Bhi, const __nv_bfloat16* __restrict__ Blo,
    float* __restrict__ C) {
    constexpr int K = 128, BM = 128;
    constexpr int LDA = K + 8;                       // bf16 elems
    constexpr int LDB = N + 8;
    // smem elem offsets (bf16): Bhi | Blo | A[2 buf][2 hl][128][LDA]
    constexpr int BH = 0;
    constexpr int BL = K * LDB;
    constexpr int AOFF = 2 * K * LDB;
    extern __shared__ __nv_bfloat16 sm[];

    const int tid = threadIdx.x, wid = tid >> 5;
    const uint32_t sbase = smem_u32(sm);

    // stage B (hi/lo) once
    constexpr int NQ = N / 8;
    for (int idx = tid; idx < K * NQ; idx += 512) {
        int r = idx / NQ, cq = idx % NQ;
        *(uint4*)(sm + BH + r * LDB + cq * 8) = ((const uint4*)(Bhi + (size_t)r * N))[cq];
        *(uint4*)(sm + BL + r * LDB + cq * 8) = ((const uint4*)(Blo + (size_t)r * N))[cq];
    }

    // A tile stage via cp.async: 4096 16B chunks (2 hl x 128 rows x 16), 8 per thread
    auto stageA = [&](int buf, int t) {
#pragma unroll
        for (int p = 0; p < 8; p++) {
            int idx = p * 512 + tid;
            int hl = idx >> 11;
            int r = (idx >> 4) & 127;
            int c8 = idx & 15;
            int grow = t * BM + r;
            const __nv_bfloat16* sp = (hl ? Alo : Ahi) +
                (size_t)(grow < N_NODES ? grow : 0) * K + c8 * 8;
            int sz = (grow < N_NODES) ? 16 : 0;
            uint32_t dst = sbase + (uint32_t)(AOFF + (buf * 2 + hl) * BM * LDA + r * LDA) * 2
                         + (uint32_t)c8 * 16;
            cp16(dst, sp, sz);
        }
    };

    // warp tiling: 4 (m) x 4 (n); warp tile 32 x WN
    constexpr int WN = N / 4;                        // 32 or 16
    constexpr int NFRAG = WN / 16;                   // 2 or 1
    const int wm = (wid >> 2) * 32;
    const int wn = (wid & 3) * WN;

    const int t0 = blockIdx.x;
    if (t0 < NT) stageA(0, t0);
    CP_COMMIT();
    __syncthreads();                                  // B visible

    int buf = 0;
    for (int t = t0; t < NT; t += gridDim.x) {
        int tn = t + (int)gridDim.x;
        if (tn < NT) stageA(buf ^ 1, tn);
        CP_COMMIT();
        CP_WAIT1();                                   // current tile's group done
        __syncthreads();

        const __nv_bfloat16* sAh = sm + AOFF + (buf * 2 + 0) * BM * LDA;
        const __nv_bfloat16* sAl = sm + AOFF + (buf * 2 + 1) * BM * LDA;

        wmma::fragment<wmma::accumulator, 16, 16, 16, float> acc[2][NFRAG];
#pragma unroll
        for (int i = 0; i < 2; i++)
#pragma unroll
            for (int j = 0; j < NFRAG; j++) wmma::fill_fragment(acc[i][j], 0.0f);

#pragma unroll
        for (int k = 0; k < K; k += 16) {
            wmma::fragment<wmma::matrix_a, 16, 16, 16, __nv_bfloat16, wmma::row_major> ah[2], al[2];
#pragma unroll
            for (int i = 0; i < 2; i++) {
                wmma::load_matrix_sync(ah[i], sAh + (wm + i * 16) * LDA + k, LDA);
                wmma::load_matrix_sync(al[i], sAl + (wm + i * 16) * LDA + k, LDA);
            }
#pragma unroll
            for (int j = 0; j < NFRAG; j++) {
                wmma::fragment<wmma::matrix_b, 16, 16, 16, __nv_bfloat16, wmma::row_major> bh, bl;
                wmma::load_matrix_sync(bh, sm + BH + k * LDB + wn + j * 16, LDB);
                wmma::load_matrix_sync(bl, sm + BL + k * LDB + wn + j * 16, LDB);
#pragma unroll
                for (int i = 0; i < 2; i++) {
                    wmma::mma_sync(acc[i][j], ah[i], bh, acc[i][j]);
                    wmma::mma_sync(acc[i][j], ah[i], bl, acc[i][j]);
                    wmma::mma_sync(acc[i][j], al[i], bh, acc[i][j]);
                }
            }
        }

        // store: 40000 % 16 == 0, so 16-row fragments are all-in or all-out
#pragma unroll
        for (int i = 0; i < 2; i++) {
            int grow = t * BM + wm + i * 16;
            if (grow < N_NODES) {
#pragma unroll
                for (int j = 0; j < NFRAG; j++)
                    wmma::store_matrix_sync(C + (size_t)grow * N + wn + j * 16, acc[i][j],
                                            N, wmma::mem_row_major);
            }
        }
        __syncthreads();
        buf ^= 1;
    }
}

// ---------------- gather layer 1: one warp per node; emits relu(agg+b1) as bf16 hi/lo ----------------
__global__ void k_gather1(const float* __restrict__ b1) {
    int node = (blockIdx.x * blockDim.x + threadIdx.x) >> 5;
    if (node >= N_NODES) return;
    int lane = threadIdx.x & 31;

    float dd = g_dinv[node];
    float self = dd * dd;
    float4 acc = ((const float4*)(g_h1 + (size_t)node * DH))[lane];
    acc.x *= self; acc.y *= self; acc.z *= self; acc.w *= self;

    int n = min(g_cnt[node], PAD);
    const int* lst = g_eslots + (size_t)node * PAD;
    int e = 0;
    for (; e + 4 <= n; e += 4) {
        int4 s4 = *(const int4*)(lst + e);
        float w0 = g_dinv[s4.x] * dd, w1 = g_dinv[s4.y] * dd;
        float w2 = g_dinv[s4.z] * dd, w3 = g_dinv[s4.w] * dd;
        float4 v0 = ((const float4*)(g_h1 + (size_t)s4.x * DH))[lane];
        float4 v1 = ((const float4*)(g_h1 + (size_t)s4.y * DH))[lane];
        float4 v2 = ((const float4*)(g_h1 + (size_t)s4.z * DH))[lane];
        float4 v3 = ((const float4*)(g_h1 + (size_t)s4.w * DH))[lane];
        acc.x = fmaf(v0.x, w0, fmaf(v1.x, w1, fmaf(v2.x, w2, fmaf(v3.x, w3, acc.x))));
        acc.y = fmaf(v0.y, w0, fmaf(v1.y, w1, fmaf(v2.y, w2, fmaf(v3.y, w3, acc.y))));
        acc.z = fmaf(v0.z, w0, fmaf(v1.z, w1, fmaf(v2.z, w2, fmaf(v3.z, w3, acc.z))));
        acc.w = fmaf(v0.w, w0, fmaf(v1.w, w1, fmaf(v2.w, w2, fmaf(v3.w, w3, acc.w))));
    }
    for (; e < n; e++) {
        int s = lst[e];
        float w = g_dinv[s] * dd;
        float4 v = ((const float4*)(g_h1 + (size_t)s * DH))[lane];
        acc.x = fmaf(v.x, w, acc.x);
        acc.y = fmaf(v.y, w, acc.y);
        acc.z = fmaf(v.z, w, acc.z);
        acc.w = fmaf(v.w, w, acc.w);
    }
    float4 bb = ((const float4*)b1)[lane];
    float t0 = fmaxf(acc.x + bb.x, 0.0f), t1 = fmaxf(acc.y + bb.y, 0.0f);
    float t2 = fmaxf(acc.z + bb.z, 0.0f), t3 = fmaxf(acc.w + bb.w, 0.0f);
    uint2 h, l;
    split2(t0, t1, h.x, l.x);
    split2(t2, t3, h.y, l.y);
    ((uint2*)(g_a2hi + (size_t)node * DH))[lane] = h;
    ((uint2*)(g_a2lo + (size_t)node * DH))[lane] = l;
}

// ---------------- gather layer 2 (C=64): half-warp per node, + b2 ----------------
__global__ void k_gather2(const float* __restrict__ b2, float* __restrict__ out) {
    int gw = (blockIdx.x * blockDim.x + threadIdx.x) >> 5;
    int lane = threadIdx.x & 31;
    int node = gw * 2 + (lane >> 4);
    if (node >= N_NODES) return;
    int l = lane & 15;

    float dd = g_dinv[node];
    float self = dd * dd;
    float4 acc = ((const float4*)(g_h2 + (size_t)node * DOUT))[l];
    acc.x *= self; acc.y *= self; acc.z *= self; acc.w *= self;

    int n = min(g_cnt[node], PAD);
    const int* lst = g_eslots + (size_t)node * PAD;
    int e = 0;
    for (; e + 4 <= n; e += 4) {
        int4 s4 = *(const int4*)(lst + e);
        float w0 = g_dinv[s4.x] * dd, w1 = g_dinv[s4.y] * dd;
        float w2 = g_dinv[s4.z] * dd, w3 = g_dinv[s4.w] * dd;
        float4 v0 = ((const float4*)(g_h2 + (size_t)s4.x * DOUT))[l];
        float4 v1 = ((const float4*)(g_h2 + (size_t)s4.y * DOUT))[l];
        float4 v2 = ((const float4*)(g_h2 + (size_t)s4.z * DOUT))[l];
        float4 v3 = ((const float4*)(g_h2 + (size_t)s4.w * DOUT))[l];
        acc.x = fmaf(v0.x, w0, fmaf(v1.x, w1, fmaf(v2.x, w2, fmaf(v3.x, w3, acc.x))));
        acc.y = fmaf(v0.y, w0, fmaf(v1.y, w1, fmaf(v2.y, w2, fmaf(v3.y, w3, acc.y))));
        acc.z = fmaf(v0.z, w0, fmaf(v1.z, w1, fmaf(v2.z, w2, fmaf(v3.z, w3, acc.z))));
        acc.w = fmaf(v0.w, w0, fmaf(v1.w, w1, fmaf(v2.w, w2, fmaf(v3.w, w3, acc.w))));
    }
    for (; e < n; e++) {
        int s = lst[e];
        float w = g_dinv[s] * dd;
        float4 v = ((const float4*)(g_h2 + (size_t)s * DOUT))[l];
        acc.x = fmaf(v.x, w, acc.x);
        acc.y = fmaf(v.y, w, acc.y);
        acc.z = fmaf(v.z, w, acc.z);
        acc.w = fmaf(v.w, w, acc.w);
    }
    float4 b = ((const float4*)b2)[l];
    acc.x += b.x; acc.y += b.y; acc.z += b.z; acc.w += b.w;
    ((float4*)(out + (size_t)node * DOUT))[l] = acc;
}

// ---------------- launch ----------------
extern "C" void kernel_launch(void* const* d_in, const int* in_sizes, int n_in,
                              void* d_out, int out_size) {
    const float* x  = (const float*)d_in[0];
    const void*  ei = d_in[1];
    const float* W1 = (const float*)d_in[2];
    const float* b1 = (const float*)d_in[3];
    const float* W2 = (const float*)d_in[4];
    const float* b2 = (const float*)d_in[5];
    float*       out = (float*)d_out;

    float *h1, *h2;
    __nv_bfloat16 *xhi, *xlo, *a2hi, *a2lo, *b1hi, *b1lo, *b2hi, *b2lo;
    cudaGetSymbolAddress((void**)&h1, g_h1);
    cudaGetSymbolAddress((void**)&h2, g_h2);
    cudaGetSymbolAddress((void**)&xhi, g_xhi);
    cudaGetSymbolAddress((void**)&xlo, g_xlo);
    cudaGetSymbolAddress((void**)&a2hi, g_a2hi);
    cudaGetSymbolAddress((void**)&a2lo, g_a2lo);
    cudaGetSymbolAddress((void**)&b1hi, g_b1hi);
    cudaGetSymbolAddress((void**)&b1lo, g_b1lo);
    cudaGetSymbolAddress((void**)&b2hi, g_b2hi);
    cudaGetSymbolAddress((void**)&b2lo, g_b2lo);

    // smem (bf16 elems *2 bytes): B hi/lo (128*(N+8)*2) + A double-buffered hi/lo (4*128*136)
    const int SM1 = (2 * 128 * (DH + 8) + 4 * 128 * 136) * 2;     // 208896 B
    const int SM2 = (2 * 128 * (DOUT + 8) + 4 * 128 * 136) * 2;   // 176128 B
    cudaFuncSetAttribute(k_gemm_pipe<DH>,   cudaFuncAttributeMaxDynamicSharedMemorySize, SM1);
    cudaFuncSetAttribute(k_gemm_pipe<DOUT>, cudaFuncAttributeMaxDynamicSharedMemorySize, SM2);

    const int T = 256;

    // prep: init (zero+detect+W split), x split, padded-list fill, dinv
    k_init<<<(N_NODES + T - 1) / T, T>>>((const int*)ei, W1, W2);
    k_cvtx<<<(N_NODES * DIN / 4 + T - 1) / T, T>>>(x);
    k_fill<<<(N_EDGES + T - 1) / T, T>>>(ei);
    k_dinv<<<(N_NODES + T - 1) / T, T>>>();

    // layer 1
    k_gemm_pipe<DH><<<GEMM_GRID, 512, SM1>>>(xhi, xlo, b1hi, b1lo, h1);
    k_gather1<<<(N_NODES * 32 + T - 1) / T, T>>>(b1);

    // layer 2
    k_gemm_pipe<DOUT><<<GEMM_GRID, 512, SM2>>>(a2hi, a2lo, b2hi, b2lo, h2);
    k_gather2<<<(N_NODES / 2 * 32 + T - 1) / T, T>>>(b2, out);
}

// round 16
// speedup vs baseline: 1.4068x; 1.4068x over previous
#include <cuda_runtime.h>
#include <cuda_bf16.h>
#include <mma.h>
#include <cstdint>

using namespace nvcuda;

#define N_NODES 40000
#define N_EDGES 640000
#define DIN 128
#define DH 128
#define DOUT 64
#define PAD 64                                       // max in-degree slots per node

#define NT ((N_NODES + 127) / 128)                   // 313 M-tiles
#define GEMM_GRID 152

// ---------------- scratch (no allocations allowed) ----------------
__device__ int   g_is64;
__device__ int   g_cnt[N_NODES];
__device__ __align__(16) int g_eslots[(size_t)N_NODES * PAD];   // padded adjacency (src ids)
__device__ float g_dinv[N_NODES];
__device__ float g_h1[(size_t)N_NODES * DH];         // gemm1 out (fp32)
__device__ float g_h2[(size_t)N_NODES * DOUT];       // gemm2 out (fp32)
// bf16 hi/lo split operands
__device__ __align__(16) __nv_bfloat16 g_xhi[(size_t)N_NODES * DIN];
__device__ __align__(16) __nv_bfloat16 g_xlo[(size_t)N_NODES * DIN];
__device__ __align__(16) __nv_bfloat16 g_a2hi[(size_t)N_NODES * DH];
__device__ __align__(16) __nv_bfloat16 g_a2lo[(size_t)N_NODES * DH];
__device__ __align__(16) __nv_bfloat16 g_b1hi[DIN * DH];   // row-major [k][n]
__device__ __align__(16) __nv_bfloat16 g_b1lo[DIN * DH];
__device__ __align__(16) __nv_bfloat16 g_b2hi[DH * DOUT];
__device__ __align__(16) __nv_bfloat16 g_b2lo[DH * DOUT];

// ---------------- helpers ----------------
__device__ __forceinline__ uint32_t smem_u32(const void* p) {
    uint32_t a;
    asm("{ .reg .u64 t; cvta.to.shared.u64 t, %1; cvt.u32.u64 %0, t; }" : "=r"(a) : "l"(p));
    return a;
}
__device__ __forceinline__ void cp16(uint32_t dst, const void* src, int sz) {
    asm volatile("cp.async.cg.shared.global [%0], [%1], 16, %2;"
                 :: "r"(dst), "l"(src), "r"(sz) : "memory");
}
#define CP_COMMIT() asm volatile("cp.async.commit_group;" ::: "memory")
#define CP_WAIT1()  asm volatile("cp.async.wait_group 1;" ::: "memory")

__device__ __forceinline__ void split2(float a, float b, uint32_t& hi, uint32_t& lo) {
    __nv_bfloat16 ha = __float2bfloat16(a), hb = __float2bfloat16(b);
    float ra = a - __bfloat162float(ha), rb = b - __bfloat162float(hb);
    __nv_bfloat16 la = __float2bfloat16(ra), lb = __float2bfloat16(rb);
    hi = (uint32_t)__bfloat16_as_ushort(ha) | ((uint32_t)__bfloat16_as_ushort(hb) << 16);
    lo = (uint32_t)__bfloat16_as_ushort(la) | ((uint32_t)__bfloat16_as_ushort(lb) << 16);
}

// ---------------- init: zero counts + dtype detect + weight split (fused) ----------------
__global__ void k_init(const int* __restrict__ ei,
                       const float* __restrict__ W1, const float* __restrict__ W2) {
    int i = blockIdx.x * blockDim.x + threadIdx.x;
    if (i < N_NODES) g_cnt[i] = 0;
    if (i < DIN * DH) {
        float v = W1[i];
        __nv_bfloat16 h = __float2bfloat16(v);
        g_b1hi[i] = h;
        g_b1lo[i] = __float2bfloat16(v - __bfloat162float(h));
    }
    int j = i - DIN * DH;
    if (j >= 0 && j < DH * DOUT) {
        float v = W2[j];
        __nv_bfloat16 h = __float2bfloat16(v);
        g_b2hi[j] = h;
        g_b2lo[j] = __float2bfloat16(v - __bfloat162float(h));
    }
    if (blockIdx.x == 0) {
        __shared__ int any_nz;
        if (threadIdx.x == 0) any_nz = 0;
        __syncthreads();
        int nz = 0;
        for (int t = threadIdx.x; t < 4096; t += blockDim.x)
            if (ei[2 * t + 1] != 0) nz = 1;
        if (nz) any_nz = 1;
        __syncthreads();
        if (threadIdx.x == 0) g_is64 = any_nz ? 0 : 1;
    }
}

__device__ __forceinline__ int edge_idx(const void* ei, int which, int e, int is64) {
    if (is64) return (int)((const long long*)ei)[(size_t)which * N_EDGES + e];
    return ((const int*)ei)[which * N_EDGES + e];
}

// ---------------- x -> hi/lo bf16 ----------------
__global__ void k_cvtx(const float* __restrict__ x) {
    int idx = blockIdx.x * blockDim.x + threadIdx.x;          // float4 index
    if (idx < N_NODES * DIN / 4) {
        float4 v = ((const float4*)x)[idx];
        uint2 h, l;
        split2(v.x, v.y, h.x, l.x);
        split2(v.z, v.w, h.y, l.y);
        ((uint2*)g_xhi)[idx] = h;
        ((uint2*)g_xlo)[idx] = l;
    }
}

// ---------------- padded-list fill + dinv ----------------
__global__ void k_fill(const void* __restrict__ ei) {
    int e = blockIdx.x * blockDim.x + threadIdx.x;
    if (e < N_EDGES) {
        int is64 = g_is64;
        int d = edge_idx(ei, 1, e, is64);
        int s = edge_idx(ei, 0, e, is64);
        if ((unsigned)d < N_NODES && (unsigned)s < N_NODES) {
            int pos = atomicAdd(&g_cnt[d], 1);
            if (pos < PAD) g_eslots[(size_t)d * PAD + pos] = s;
        }
    }
}

__global__ void k_dinv() {
    int i = blockIdx.x * blockDim.x + threadIdx.x;
    if (i < N_NODES) g_dinv[i] = rsqrtf((float)(g_cnt[i] + 1));   // +1 self-loop
}

// ---------------- pipelined WMMA bf16 GEMM: C[40000,N] = A[40000,128] @ B[128,N] ----------------
// R13 tiling (256 threads, 4x2 warp grid, 32xWN warp tiles) + cp.async double-buffered A.
// A pre-split bf16 hi/lo in GMEM; B SMEM-resident. fp32 accum: Ah*Bh + Ah*Bl + Al*Bh.
template <int N>
__global__ void __launch_bounds__(256, 1) k_gemm_pipe(
    const __nv_bfloat16* __restrict__ Ahi, const __nv_bfloat16* __restrict__ Alo,
    const __nv_bfloat16* __restrict__ Bhi, const __nv_bfloat16* __restrict__ Blo,
    float* __restrict__ C) {
    constexpr int K = 128, BM = 128;
    constexpr int LDA = K + 8;                       // bf16 elems
    constexpr int LDB = N + 8;
    // smem elem offsets (bf16): Bhi | Blo | A[2 buf][2 hl][128][LDA]
    constexpr int BH = 0;
    constexpr int BL = K * LDB;
    constexpr int AOFF = 2 * K * LDB;
    extern __shared__ __nv_bfloat16 sm[];

    const int tid = threadIdx.x, wid = tid >> 5;
    const uint32_t sbase = smem_u32(sm);

    // stage B (hi/lo) once
    constexpr int NQ = N / 8;
    for (int idx = tid; idx < K * NQ; idx += 256) {
        int r = idx / NQ, cq = idx % NQ;
        *(uint4*)(sm + BH + r * LDB + cq * 8) = ((const uint4*)(Bhi + (size_t)r * N))[cq];
        *(uint4*)(sm + BL + r * LDB + cq * 8) = ((const uint4*)(Blo + (size_t)r * N))[cq];
    }

    // A tile stage via cp.async: 4096 16B chunks (2 hl x 128 rows x 16), 16 per thread
    auto stageA = [&](int buf, int t) {
#pragma unroll
        for (int p = 0; p < 16; p++) {
            int idx = p * 256 + tid;
            int hl = idx >> 11;
            int r = (idx >> 4) & 127;
            int c8 = idx & 15;
            int grow = t * BM + r;
            const __nv_bfloat16* sp = (hl ? Alo : Ahi) +
                (size_t)(grow < N_NODES ? grow : 0) * K + c8 * 8;
            int sz = (grow < N_NODES) ? 16 : 0;
            uint32_t dst = sbase + (uint32_t)(AOFF + (buf * 2 + hl) * BM * LDA + r * LDA) * 2
                         + (uint32_t)c8 * 16;
            cp16(dst, sp, sz);
        }
    };

    // warp tiling (R13): 4 (m) x 2 (n); warp tile 32 x WN
    constexpr int WN = (N == 128) ? 64 : 32;
    constexpr int NFRAG = WN / 16;                   // 4 or 2
    const int wm = (wid >> 1) * 32;
    const int wn = (wid & 1) * WN;

    const int t0 = blockIdx.x;
    if (t0 < NT) stageA(0, t0);
    CP_COMMIT();
    __syncthreads();                                  // B visible

    int buf = 0;
    for (int t = t0; t < NT; t += gridDim.x) {
        int tn = t + (int)gridDim.x;
        if (tn < NT) stageA(buf ^ 1, tn);
        CP_COMMIT();
        CP_WAIT1();                                   // current tile's group done
        __syncthreads();

        const __nv_bfloat16* sAh = sm + AOFF + (buf * 2 + 0) * BM * LDA;
        const __nv_bfloat16* sAl = sm + AOFF + (buf * 2 + 1) * BM * LDA;

        wmma::fragment<wmma::accumulator, 16, 16, 16, float> acc[2][NFRAG];
#pragma unroll
        for (int i = 0; i < 2; i++)
#pragma unroll
            for (int j = 0; j < NFRAG; j++) wmma::fill_fragment(acc[i][j], 0.0f);

#pragma unroll
        for (int k = 0; k < K; k += 16) {
            wmma::fragment<wmma::matrix_a, 16, 16, 16, __nv_bfloat16, wmma::row_major> ah[2], al[2];
#pragma unroll
            for (int i = 0; i < 2; i++) {
                wmma::load_matrix_sync(ah[i], sAh + (wm + i * 16) * LDA + k, LDA);
                wmma::load_matrix_sync(al[i], sAl + (wm + i * 16) * LDA + k, LDA);
            }
#pragma unroll
            for (int j = 0; j < NFRAG; j++) {
                wmma::fragment<wmma::matrix_b, 16, 16, 16, __nv_bfloat16, wmma::row_major> bh, bl;
                wmma::load_matrix_sync(bh, sm + BH + k * LDB + wn + j * 16, LDB);
                wmma::load_matrix_sync(bl, sm + BL + k * LDB + wn + j * 16, LDB);
#pragma unroll
                for (int i = 0; i < 2; i++) {
                    wmma::mma_sync(acc[i][j], ah[i], bh, acc[i][j]);
                    wmma::mma_sync(acc[i][j], ah[i], bl, acc[i][j]);
                    wmma::mma_sync(acc[i][j], al[i], bh, acc[i][j]);
                }
            }
        }

        // store: 40000 % 16 == 0, so 16-row fragments are all-in or all-out
#pragma unroll
        for (int i = 0; i < 2; i++) {
            int grow = t * BM + wm + i * 16;
            if (grow < N_NODES) {
#pragma unroll
                for (int j = 0; j < NFRAG; j++)
                    wmma::store_matrix_sync(C + (size_t)grow * N + wn + j * 16, acc[i][j],
                                            N, wmma::mem_row_major);
            }
        }
        __syncthreads();
        buf ^= 1;
    }
}

// ---------------- gather layer 1: one warp per node; emits relu(agg+b1) as bf16 hi/lo ----------------
__global__ void k_gather1(const float* __restrict__ b1) {
    int node = (blockIdx.x * blockDim.x + threadIdx.x) >> 5;
    if (node >= N_NODES) return;
    int lane = threadIdx.x & 31;

    float dd = g_dinv[node];
    float self = dd * dd;
    float4 acc = ((const float4*)(g_h1 + (size_t)node * DH))[lane];
    acc.x *= self; acc.y *= self; acc.z *= self; acc.w *= self;

    int n = min(g_cnt[node], PAD);
    const int* lst = g_eslots + (size_t)node * PAD;
    int e = 0;
    for (; e + 4 <= n; e += 4) {
        int4 s4 = *(const int4*)(lst + e);
        float w0 = g_dinv[s4.x] * dd, w1 = g_dinv[s4.y] * dd;
        float w2 = g_dinv[s4.z] * dd, w3 = g_dinv[s4.w] * dd;
        float4 v0 = ((const float4*)(g_h1 + (size_t)s4.x * DH))[lane];
        float4 v1 = ((const float4*)(g_h1 + (size_t)s4.y * DH))[lane];
        float4 v2 = ((const float4*)(g_h1 + (size_t)s4.z * DH))[lane];
        float4 v3 = ((const float4*)(g_h1 + (size_t)s4.w * DH))[lane];
        acc.x = fmaf(v0.x, w0, fmaf(v1.x, w1, fmaf(v2.x, w2, fmaf(v3.x, w3, acc.x))));
        acc.y = fmaf(v0.y, w0, fmaf(v1.y, w1, fmaf(v2.y, w2, fmaf(v3.y, w3, acc.y))));
        acc.z = fmaf(v0.z, w0, fmaf(v1.z, w1, fmaf(v2.z, w2, fmaf(v3.z, w3, acc.z))));
        acc.w = fmaf(v0.w, w0, fmaf(v1.w, w1, fmaf(v2.w, w2, fmaf(v3.w, w3, acc.w))));
    }
    for (; e < n; e++) {
        int s = lst[e];
        float w = g_dinv[s] * dd;
        float4 v = ((const float4*)(g_h1 + (size_t)s * DH))[lane];
        acc.x = fmaf(v.x, w, acc.x);
        acc.y = fmaf(v.y, w, acc.y);
        acc.z = fmaf(v.z, w, acc.z);
        acc.w = fmaf(v.w, w, acc.w);
    }
    float4 bb = ((const float4*)b1)[lane];
    float t0 = fmaxf(acc.x + bb.x, 0.0f), t1 = fmaxf(acc.y + bb.y, 0.0f);
    float t2 = fmaxf(acc.z + bb.z, 0.0f), t3 = fmaxf(acc.w + bb.w, 0.0f);
    uint2 h, l;
    split2(t0, t1, h.x, l.x);
    split2(t2, t3, h.y, l.y);
    ((uint2*)(g_a2hi + (size_t)node * DH))[lane] = h;
    ((uint2*)(g_a2lo + (size_t)node * DH))[lane] = l;
}

// ---------------- gather layer 2 (C=64): half-warp per node, + b2 ----------------
__global__ void k_gather2(const float* __restrict__ b2, float* __restrict__ out) {
    int gw = (blockIdx.x * blockDim.x + threadIdx.x) >> 5;
    int lane = threadIdx.x & 31;
    int node = gw * 2 + (lane >> 4);
    if (node >= N_NODES) return;
    int l = lane & 15;

    float dd = g_dinv[node];
    float self = dd * dd;
    float4 acc = ((const float4*)(g_h2 + (size_t)node * DOUT))[l];
    acc.x *= self; acc.y *= self; acc.z *= self; acc.w *= self;

    int n = min(g_cnt[node], PAD);
    const int* lst = g_eslots + (size_t)node * PAD;
    int e = 0;
    for (; e + 4 <= n; e += 4) {
        int4 s4 = *(const int4*)(lst + e);
        float w0 = g_dinv[s4.x] * dd, w1 = g_dinv[s4.y] * dd;
        float w2 = g_dinv[s4.z] * dd, w3 = g_dinv[s4.w] * dd;
        float4 v0 = ((const float4*)(g_h2 + (size_t)s4.x * DOUT))[l];
        float4 v1 = ((const float4*)(g_h2 + (size_t)s4.y * DOUT))[l];
        float4 v2 = ((const float4*)(g_h2 + (size_t)s4.z * DOUT))[l];
        float4 v3 = ((const float4*)(g_h2 + (size_t)s4.w * DOUT))[l];
        acc.x = fmaf(v0.x, w0, fmaf(v1.x, w1, fmaf(v2.x, w2, fmaf(v3.x, w3, acc.x))));
        acc.y = fmaf(v0.y, w0, fmaf(v1.y, w1, fmaf(v2.y, w2, fmaf(v3.y, w3, acc.y))));
        acc.z = fmaf(v0.z, w0, fmaf(v1.z, w1, fmaf(v2.z, w2, fmaf(v3.z, w3, acc.z))));
        acc.w = fmaf(v0.w, w0, fmaf(v1.w, w1, fmaf(v2.w, w2, fmaf(v3.w, w3, acc.w))));
    }
    for (; e < n; e++) {
        int s = lst[e];
        float w = g_dinv[s] * dd;
        float4 v = ((const float4*)(g_h2 + (size_t)s * DOUT))[l];
        acc.x = fmaf(v.x, w, acc.x);
        acc.y = fmaf(v.y, w, acc.y);
        acc.z = fmaf(v.z, w, acc.z);
        acc.w = fmaf(v.w, w, acc.w);
    }
    float4 b = ((const float4*)b2)[l];
    acc.x += b.x; acc.y += b.y; acc.z += b.z; acc.w += b.w;
    ((float4*)(out + (size_t)node * DOUT))[l] = acc;
}

// ---------------- launch ----------------
extern "C" void kernel_launch(void* const* d_in, const int* in_sizes, int n_in,
                              void* d_out, int out_size) {
    const float* x  = (const float*)d_in[0];
    const void*  ei = d_in[1];
    const float* W1 = (const float*)d_in[2];
    const float* b1 = (const float*)d_in[3];
    const float* W2 = (const float*)d_in[4];
    const float* b2 = (const float*)d_in[5];
    float*       out = (float*)d_out;

    float *h1, *h2;
    __nv_bfloat16 *xhi, *xlo, *a2hi, *a2lo, *b1hi, *b1lo, *b2hi, *b2lo;
    cudaGetSymbolAddress((void**)&h1, g_h1);
    cudaGetSymbolAddress((void**)&h2, g_h2);
    cudaGetSymbolAddress((void**)&xhi, g_xhi);
    cudaGetSymbolAddress((void**)&xlo, g_xlo);
    cudaGetSymbolAddress((void**)&a2hi, g_a2hi);
    cudaGetSymbolAddress((void**)&a2lo, g_a2lo);
    cudaGetSymbolAddress((void**)&b1hi, g_b1hi);
    cudaGetSymbolAddress((void**)&b1lo, g_b1lo);
    cudaGetSymbolAddress((void**)&b2hi, g_b2hi);
    cudaGetSymbolAddress((void**)&b2lo, g_b2lo);

    // smem (bf16 elems *2 bytes): B hi/lo (2*128*(N+8)) + A double-buffered hi/lo (4*128*136)
    const int SM1 = (2 * 128 * (DH + 8) + 4 * 128 * 136) * 2;     // 208896 B
    const int SM2 = (2 * 128 * (DOUT + 8) + 4 * 128 * 136) * 2;   // 176128 B
    cudaFuncSetAttribute(k_gemm_pipe<DH>,   cudaFuncAttributeMaxDynamicSharedMemorySize, SM1);
    cudaFuncSetAttribute(k_gemm_pipe<DOUT>, cudaFuncAttributeMaxDynamicSharedMemorySize, SM2);

    const int T = 256;

    // prep: init (zero+detect+W split), x split, padded-list fill, dinv
    k_init<<<(N_NODES + T - 1) / T, T>>>((const int*)ei, W1, W2);
    k_cvtx<<<(N_NODES * DIN / 4 + T - 1) / T, T>>>(x);
    k_fill<<<(N_EDGES + T - 1) / T, T>>>(ei);
    k_dinv<<<(N_NODES + T - 1) / T, T>>>();

    // layer 1
    k_gemm_pipe<DH><<<GEMM_GRID, T, SM1>>>(xhi, xlo, b1hi, b1lo, h1);
    k_gather1<<<(N_NODES * 32 + T - 1) / T, T>>>(b1);

    // layer 2
    k_gemm_pipe<DOUT><<<GEMM_GRID, T, SM2>>>(a2hi, a2lo, b2hi, b2lo, h2);
    k_gather2<<<(N_NODES / 2 * 32 + T - 1) / T, T>>>(b2, out);
}

// round 17
// speedup vs baseline: 1.4582x; 1.0366x over previous
#include <cuda_runtime.h>
#include <cuda_bf16.h>
#include <mma.h>
#include <cstdint>

using namespace nvcuda;

#define N_NODES 40000
#define N_EDGES 640000
#define DIN 128
#define DH 128
#define DOUT 64
#define PAD 64                                       // max in-degree slots per node

#define NT ((N_NODES + 127) / 128)                   // 313 M-tiles
#define GEMM_GRID 152

// ---------------- scratch (no allocations allowed) ----------------
__device__ int   g_is64;
__device__ int   g_cnt[N_NODES];
__device__ __align__(16) int g_eslots[(size_t)N_NODES * PAD];   // padded adjacency (src ids)
__device__ float g_h1[(size_t)N_NODES * DH];         // gemm1 out (fp32)
__device__ float g_h2[(size_t)N_NODES * DOUT];       // gemm2 out (fp32)
// bf16 hi/lo split operands
__device__ __align__(16) __nv_bfloat16 g_xhi[(size_t)N_NODES * DIN];
__device__ __align__(16) __nv_bfloat16 g_xlo[(size_t)N_NODES * DIN];
__device__ __align__(16) __nv_bfloat16 g_a2hi[(size_t)N_NODES * DH];
__device__ __align__(16) __nv_bfloat16 g_a2lo[(size_t)N_NODES * DH];
__device__ __align__(16) __nv_bfloat16 g_b1hi[DIN * DH];   // row-major [k][n]
__device__ __align__(16) __nv_bfloat16 g_b1lo[DIN * DH];
__device__ __align__(16) __nv_bfloat16 g_b2hi[DH * DOUT];
__device__ __align__(16) __nv_bfloat16 g_b2lo[DH * DOUT];

// ---------------- helpers ----------------
__device__ __forceinline__ uint32_t smem_u32(const void* p) {
    uint32_t a;
    asm("{ .reg .u64 t; cvta.to.shared.u64 t, %1; cvt.u32.u64 %0, t; }" : "=r"(a) : "l"(p));
    return a;
}
__device__ __forceinline__ void cp16(uint32_t dst, const void* src, int sz) {
    asm volatile("cp.async.cg.shared.global [%0], [%1], 16, %2;"
                 :: "r"(dst), "l"(src), "r"(sz) : "memory");
}
#define CP_COMMIT() asm volatile("cp.async.commit_group;" ::: "memory")
#define CP_WAIT1()  asm volatile("cp.async.wait_group 1;" ::: "memory")

__device__ __forceinline__ void split2(float a, float b, uint32_t& hi, uint32_t& lo) {
    __nv_bfloat16 ha = __float2bfloat16(a), hb = __float2bfloat16(b);
    float ra = a - __bfloat162float(ha), rb = b - __bfloat162float(hb);
    __nv_bfloat16 la = __float2bfloat16(ra), lb = __float2bfloat16(rb);
    hi = (uint32_t)__bfloat16_as_ushort(ha) | ((uint32_t)__bfloat16_as_ushort(hb) << 16);
    lo = (uint32_t)__bfloat16_as_ushort(la) | ((uint32_t)__bfloat16_as_ushort(lb) << 16);
}

// ---------------- fused prep: x split + zero counts + dtype detect + weight split ----------------
#define NV4 (N_NODES * DIN / 4)                      // 1.28M float4 items
__global__ void k_prep(const int* __restrict__ ei, const float* __restrict__ x,
                       const float* __restrict__ W1, const float* __restrict__ W2) {
    int i = blockIdx.x * blockDim.x + threadIdx.x;
    if (i < NV4) {
        float4 v = ((const float4*)x)[i];
        uint2 h, l;
        split2(v.x, v.y, h.x, l.x);
        split2(v.z, v.w, h.y, l.y);
        ((uint2*)g_xhi)[i] = h;
        ((uint2*)g_xlo)[i] = l;
    }
    if (i < N_NODES) g_cnt[i] = 0;
    if (i < DIN * DH) {
        float v = W1[i];
        __nv_bfloat16 h = __float2bfloat16(v);
        g_b1hi[i] = h;
        g_b1lo[i] = __float2bfloat16(v - __bfloat162float(h));
    }
    int j = i - DIN * DH;
    if (j >= 0 && j < DH * DOUT) {
        float v = W2[j];
        __nv_bfloat16 h = __float2bfloat16(v);
        g_b2hi[j] = h;
        g_b2lo[j] = __float2bfloat16(v - __bfloat162float(h));
    }
    if (blockIdx.x == 0) {
        __shared__ int any_nz;
        if (threadIdx.x == 0) any_nz = 0;
        __syncthreads();
        int nz = 0;
        for (int t = threadIdx.x; t < 4096; t += blockDim.x)
            if (ei[2 * t + 1] != 0) nz = 1;
        if (nz) any_nz = 1;
        __syncthreads();
        if (threadIdx.x == 0) g_is64 = any_nz ? 0 : 1;
    }
}

__device__ __forceinline__ int edge_idx(const void* ei, int which, int e, int is64) {
    if (is64) return (int)((const long long*)ei)[(size_t)which * N_EDGES + e];
    return ((const int*)ei)[which * N_EDGES + e];
}

// ---------------- padded-list fill ----------------
__global__ void k_fill(const void* __restrict__ ei) {
    int e = blockIdx.x * blockDim.x + threadIdx.x;
    if (e < N_EDGES) {
        int is64 = g_is64;
        int d = edge_idx(ei, 1, e, is64);
        int s = edge_idx(ei, 0, e, is64);
        if ((unsigned)d < N_NODES && (unsigned)s < N_NODES) {
            int pos = atomicAdd(&g_cnt[d], 1);
            if (pos < PAD) g_eslots[(size_t)d * PAD + pos] = s;
        }
    }
}

// ---------------- pipelined WMMA bf16 GEMM (validated R16) ----------------
template <int N>
__global__ void __launch_bounds__(256, 1) k_gemm_pipe(
    const __nv_bfloat16* __restrict__ Ahi, const __nv_bfloat16* __restrict__ Alo,
    const __nv_bfloat16* __restrict__ Bhi, const __nv_bfloat16* __restrict__ Blo,
    float* __restrict__ C) {
    constexpr int K = 128, BM = 128;
    constexpr int LDA = K + 8;
    constexpr int LDB = N + 8;
    constexpr int BH = 0;
    constexpr int BL = K * LDB;
    constexpr int AOFF = 2 * K * LDB;
    extern __shared__ __nv_bfloat16 sm[];

    const int tid = threadIdx.x, wid = tid >> 5;
    const uint32_t sbase = smem_u32(sm);

    constexpr int NQ = N / 8;
    for (int idx = tid; idx < K * NQ; idx += 256) {
        int r = idx / NQ, cq = idx % NQ;
        *(uint4*)(sm + BH + r * LDB + cq * 8) = ((const uint4*)(Bhi + (size_t)r * N))[cq];
        *(uint4*)(sm + BL + r * LDB + cq * 8) = ((const uint4*)(Blo + (size_t)r * N))[cq];
    }

    auto stageA = [&](int buf, int t) {
#pragma unroll
        for (int p = 0; p < 16; p++) {
            int idx = p * 256 + tid;
            int hl = idx >> 11;
            int r = (idx >> 4) & 127;
            int c8 = idx & 15;
            int grow = t * BM + r;
            const __nv_bfloat16* sp = (hl ? Alo : Ahi) +
                (size_t)(grow < N_NODES ? grow : 0) * K + c8 * 8;
            int sz = (grow < N_NODES) ? 16 : 0;
            uint32_t dst = sbase + (uint32_t)(AOFF + (buf * 2 + hl) * BM * LDA + r * LDA) * 2
                         + (uint32_t)c8 * 16;
            cp16(dst, sp, sz);
        }
    };

    constexpr int WN = (N == 128) ? 64 : 32;
    constexpr int NFRAG = WN / 16;
    const int wm = (wid >> 1) * 32;
    const int wn = (wid & 1) * WN;

    const int t0 = blockIdx.x;
    if (t0 < NT) stageA(0, t0);
    CP_COMMIT();
    __syncthreads();

    int buf = 0;
    for (int t = t0; t < NT; t += gridDim.x) {
        int tn = t + (int)gridDim.x;
        if (tn < NT) stageA(buf ^ 1, tn);
        CP_COMMIT();
        CP_WAIT1();
        __syncthreads();

        const __nv_bfloat16* sAh = sm + AOFF + (buf * 2 + 0) * BM * LDA;
        const __nv_bfloat16* sAl = sm + AOFF + (buf * 2 + 1) * BM * LDA;

        wmma::fragment<wmma::accumulator, 16, 16, 16, float> acc[2][NFRAG];
#pragma unroll
        for (int i = 0; i < 2; i++)
#pragma unroll
            for (int j = 0; j < NFRAG; j++) wmma::fill_fragment(acc[i][j], 0.0f);

#pragma unroll
        for (int k = 0; k < K; k += 16) {
            wmma::fragment<wmma::matrix_a, 16, 16, 16, __nv_bfloat16, wmma::row_major> ah[2], al[2];
#pragma unroll
            for (int i = 0; i < 2; i++) {
                wmma::load_matrix_sync(ah[i], sAh + (wm + i * 16) * LDA + k, LDA);
                wmma::load_matrix_sync(al[i], sAl + (wm + i * 16) * LDA + k, LDA);
            }
#pragma unroll
            for (int j = 0; j < NFRAG; j++) {
                wmma::fragment<wmma::matrix_b, 16, 16, 16, __nv_bfloat16, wmma::row_major> bh, bl;
                wmma::load_matrix_sync(bh, sm + BH + k * LDB + wn + j * 16, LDB);
                wmma::load_matrix_sync(bl, sm + BL + k * LDB + wn + j * 16, LDB);
#pragma unroll
                for (int i = 0; i < 2; i++) {
                    wmma::mma_sync(acc[i][j], ah[i], bh, acc[i][j]);
                    wmma::mma_sync(acc[i][j], ah[i], bl, acc[i][j]);
                    wmma::mma_sync(acc[i][j], al[i], bh, acc[i][j]);
                }
            }
        }

#pragma unroll
        for (int i = 0; i < 2; i++) {
            int grow = t * BM + wm + i * 16;
            if (grow < N_NODES) {
#pragma unroll
                for (int j = 0; j < NFRAG; j++)
                    wmma::store_matrix_sync(C + (size_t)grow * N + wn + j * 16, acc[i][j],
                                            N, wmma::mem_row_major);
            }
        }
        __syncthreads();
        buf ^= 1;
    }
}

// ---------------- gather layer 1: one warp per node; dinv inline; emits bf16 hi/lo ----------------
__global__ void k_gather1(const float* __restrict__ b1) {
    int node = (blockIdx.x * blockDim.x + threadIdx.x) >> 5;
    if (node >= N_NODES) return;
    int lane = threadIdx.x & 31;

    int cn = g_cnt[node];
    float dd = rsqrtf((float)(cn + 1));
    float self = dd * dd;
    float4 acc = ((const float4*)(g_h1 + (size_t)node * DH))[lane];
    acc.x *= self; acc.y *= self; acc.z *= self; acc.w *= self;

    int n = min(cn, PAD);
    const int* lst = g_eslots + (size_t)node * PAD;
    int e = 0;
    for (; e + 4 <= n; e += 4) {
        int4 s4 = *(const int4*)(lst + e);
        float w0 = rsqrtf((float)(g_cnt[s4.x] + 1)) * dd;
        float w1 = rsqrtf((float)(g_cnt[s4.y] + 1)) * dd;
        float w2 = rsqrtf((float)(g_cnt[s4.z] + 1)) * dd;
        float w3 = rsqrtf((float)(g_cnt[s4.w] + 1)) * dd;
        float4 v0 = ((const float4*)(g_h1 + (size_t)s4.x * DH))[lane];
        float4 v1 = ((const float4*)(g_h1 + (size_t)s4.y * DH))[lane];
        float4 v2 = ((const float4*)(g_h1 + (size_t)s4.z * DH))[lane];
        float4 v3 = ((const float4*)(g_h1 + (size_t)s4.w * DH))[lane];
        acc.x = fmaf(v0.x, w0, fmaf(v1.x, w1, fmaf(v2.x, w2, fmaf(v3.x, w3, acc.x))));
        acc.y = fmaf(v0.y, w0, fmaf(v1.y, w1, fmaf(v2.y, w2, fmaf(v3.y, w3, acc.y))));
        acc.z = fmaf(v0.z, w0, fmaf(v1.z, w1, fmaf(v2.z, w2, fmaf(v3.z, w3, acc.z))));
        acc.w = fmaf(v0.w, w0, fmaf(v1.w, w1, fmaf(v2.w, w2, fmaf(v3.w, w3, acc.w))));
    }
    for (; e < n; e++) {
        int s = lst[e];
        float w = rsqrtf((float)(g_cnt[s] + 1)) * dd;
        float4 v = ((const float4*)(g_h1 + (size_t)s * DH))[lane];
        acc.x = fmaf(v.x, w, acc.x);
        acc.y = fmaf(v.y, w, acc.y);
        acc.z = fmaf(v.z, w, acc.z);
        acc.w = fmaf(v.w, w, acc.w);
    }
    float4 bb = ((const float4*)b1)[lane];
    float t0 = fmaxf(acc.x + bb.x, 0.0f), t1 = fmaxf(acc.y + bb.y, 0.0f);
    float t2 = fmaxf(acc.z + bb.z, 0.0f), t3 = fmaxf(acc.w + bb.w, 0.0f);
    uint2 h, l;
    split2(t0, t1, h.x, l.x);
    split2(t2, t3, h.y, l.y);
    ((uint2*)(g_a2hi + (size_t)node * DH))[lane] = h;
    ((uint2*)(g_a2lo + (size_t)node * DH))[lane] = l;
}

// ---------------- gather layer 2 (C=64): half-warp per node, dinv inline, + b2 ----------------
__global__ void k_gather2(const float* __restrict__ b2, float* __restrict__ out) {
    int gw = (blockIdx.x * blockDim.x + threadIdx.x) >> 5;
    int lane = threadIdx.x & 31;
    int node = gw * 2 + (lane >> 4);
    if (node >= N_NODES) return;
    int l = lane & 15;

    int cn = g_cnt[node];
    float dd = rsqrtf((float)(cn + 1));
    float self = dd * dd;
    float4 acc = ((const float4*)(g_h2 + (size_t)node * DOUT))[l];
    acc.x *= self; acc.y *= self; acc.z *= self; acc.w *= self;

    int n = min(cn, PAD);
    const int* lst = g_eslots + (size_t)node * PAD;
    int e = 0;
    for (; e + 4 <= n; e += 4) {
        int4 s4 = *(const int4*)(lst + e);
        float w0 = rsqrtf((float)(g_cnt[s4.x] + 1)) * dd;
        float w1 = rsqrtf((float)(g_cnt[s4.y] + 1)) * dd;
        float w2 = rsqrtf((float)(g_cnt[s4.z] + 1)) * dd;
        float w3 = rsqrtf((float)(g_cnt[s4.w] + 1)) * dd;
        float4 v0 = ((const float4*)(g_h2 + (size_t)s4.x * DOUT))[l];
        float4 v1 = ((const float4*)(g_h2 + (size_t)s4.y * DOUT))[l];
        float4 v2 = ((const float4*)(g_h2 + (size_t)s4.z * DOUT))[l];
        float4 v3 = ((const float4*)(g_h2 + (size_t)s4.w * DOUT))[l];
        acc.x = fmaf(v0.x, w0, fmaf(v1.x, w1, fmaf(v2.x, w2, fmaf(v3.x, w3, acc.x))));
        acc.y = fmaf(v0.y, w0, fmaf(v1.y, w1, fmaf(v2.y, w2, fmaf(v3.y, w3, acc.y))));
        acc.z = fmaf(v0.z, w0, fmaf(v1.z, w1, fmaf(v2.z, w2, fmaf(v3.z, w3, acc.z))));
        acc.w = fmaf(v0.w, w0, fmaf(v1.w, w1, fmaf(v2.w, w2, fmaf(v3.w, w3, acc.w))));
    }
    for (; e < n; e++) {
        int s = lst[e];
        float w = rsqrtf((float)(g_cnt[s] + 1)) * dd;
        float4 v = ((const float4*)(g_h2 + (size_t)s * DOUT))[l];
        acc.x = fmaf(v.x, w, acc.x);
        acc.y = fmaf(v.y, w, acc.y);
        acc.z = fmaf(v.z, w, acc.z);
        acc.w = fmaf(v.w, w, acc.w);
    }
    float4 b = ((const float4*)b2)[l];
    acc.x += b.x; acc.y += b.y; acc.z += b.z; acc.w += b.w;
    ((float4*)(out + (size_t)node * DOUT))[l] = acc;
}

// ---------------- launch ----------------
static cudaStream_t s_side = nullptr;
static cudaEvent_t s_e1 = nullptr, s_e2 = nullptr;

extern "C" void kernel_launch(void* const* d_in, const int* in_sizes, int n_in,
                              void* d_out, int out_size) {
    const float* x  = (const float*)d_in[0];
    const void*  ei = d_in[1];
    const float* W1 = (const float*)d_in[2];
    const float* b1 = (const float*)d_in[3];
    const float* W2 = (const float*)d_in[4];
    const float* b2 = (const float*)d_in[5];
    float*       out = (float*)d_out;

    if (!s_side) {
        cudaStreamCreateWithFlags(&s_side, cudaStreamNonBlocking);
        cudaEventCreateWithFlags(&s_e1, cudaEventDisableTiming);
        cudaEventCreateWithFlags(&s_e2, cudaEventDisableTiming);
    }

    float *h1, *h2;
    __nv_bfloat16 *xhi, *xlo, *a2hi, *a2lo, *b1hi, *b1lo, *b2hi, *b2lo;
    cudaGetSymbolAddress((void**)&h1, g_h1);
    cudaGetSymbolAddress((void**)&h2, g_h2);
    cudaGetSymbolAddress((void**)&xhi, g_xhi);
    cudaGetSymbolAddress((void**)&xlo, g_xlo);
    cudaGetSymbolAddress((void**)&a2hi, g_a2hi);
    cudaGetSymbolAddress((void**)&a2lo, g_a2lo);
    cudaGetSymbolAddress((void**)&b1hi, g_b1hi);
    cudaGetSymbolAddress((void**)&b1lo, g_b1lo);
    cudaGetSymbolAddress((void**)&b2hi, g_b2hi);
    cudaGetSymbolAddress((void**)&b2lo, g_b2lo);

    const int SM1 = (2 * 128 * (DH + 8) + 4 * 128 * 136) * 2;     // 208896 B
    const int SM2 = (2 * 128 * (DOUT + 8) + 4 * 128 * 136) * 2;   // 176128 B
    cudaFuncSetAttribute(k_gemm_pipe<DH>,   cudaFuncAttributeMaxDynamicSharedMemorySize, SM1);
    cudaFuncSetAttribute(k_gemm_pipe<DOUT>, cudaFuncAttributeMaxDynamicSharedMemorySize, SM2);

    const int T = 256;

    // fused prep (x split + zero counts + detect + W split)
    k_prep<<<(NV4 + T - 1) / T, T>>>((const int*)ei, x, W1, W2);

    // fork: fill on side stream, overlapping gemm1 on the main stream
    cudaEventRecord(s_e1, 0);
    cudaStreamWaitEvent(s_side, s_e1, 0);
    k_fill<<<(N_EDGES + T - 1) / T, T, 0, s_side>>>(ei);
    cudaEventRecord(s_e2, s_side);

    // layer 1 GEMM (independent of fill)
    k_gemm_pipe<DH><<<GEMM_GRID, T, SM1>>>(xhi, xlo, b1hi, b1lo, h1);

    // join: gather1 needs both fill and gemm1
    cudaStreamWaitEvent(0, s_e2, 0);
    k_gather1<<<(N_NODES * 32 + T - 1) / T, T>>>(b1);

    // layer 2
    k_gemm_pipe<DOUT><<<GEMM_GRID, T, SM2>>>(a2hi, a2lo, b2hi, b2lo, h2);
    k_gather2<<<(N_NODES / 2 * 32 + T - 1) / T, T>>>(b2, out);
}